// round 2
// baseline (speedup 1.0000x reference)
#include <cuda_runtime.h>

// Fixed shapes: feat [8,64,512,512] f32, label [8,1,512,512] i32
#define NCLS 19
#define BATCH 8
#define DCH 64
#define HWPX 262144               // 512*512
#define TILE_PX 1024              // 256 threads x 4 px
#define TILES_PER_BATCH 256       // HWPX / TILE_PX
#define BLOCKS_PER_BATCH 37
#define NBLOCKS (BATCH * BLOCKS_PER_BATCH)   // 296 = 2 CTAs/SM on 148 SMs
#define NTHREADS 256
#define MAX_TILES 7               // ceil(256/37)
#define GCH 2                     // channels per bin group (static smem <= 48KB)
#define EPSF 1e-6f

// Scratch (allocation-free rule: device globals)
__device__ float g_sums[BATCH][NCLS][DCH];
__device__ float g_counts[BATCH][NCLS];

// ---------------------------------------------------------------------------
__global__ void frc_zero_kernel() {
    int i = threadIdx.x;
    float* ps = &g_sums[0][0][0];
    for (int k = i; k < BATCH * NCLS * DCH; k += NTHREADS) ps[k] = 0.0f;
    float* pc = &g_counts[0][0];
    for (int k = i; k < BATCH * NCLS; k += NTHREADS) pc[k] = 0.0f;
}

// ---------------------------------------------------------------------------
// Phase 1: segmented reduction. Per-thread-private bins [class*GCH + g][thread]:
// every lane hits bank tid%32 -> conflict-free, atomic-free inner loop.
// Accumulation is thread-private, so syncs are needed ONLY around FLUSH.
__global__ __launch_bounds__(NTHREADS, 2)
void frc_accum_kernel(const float* __restrict__ feat, const int* __restrict__ label) {
    __shared__ float s_bins[NCLS * GCH * NTHREADS];   // 38912 B

    const int tid = threadIdx.x;
    const int b  = blockIdx.x / BLOCKS_PER_BATCH;
    const int r  = blockIdx.x % BLOCKS_PER_BATCH;
    const int t_lo = (r * TILES_PER_BATCH) / BLOCKS_PER_BATCH;
    const int t_hi = ((r + 1) * TILES_PER_BATCH) / BLOCKS_PER_BATCH;
    const int ntiles = t_hi - t_lo;             // 6 or 7

    // ---- Pack this thread's labels (4 px/tile) into registers, reused for all 64 channels.
    unsigned plab[MAX_TILES];
    {
        const int4* lab4 = (const int4*)(label + (size_t)b * HWPX);
        #pragma unroll
        for (int j = 0; j < MAX_TILES; j++) {
            if (j < ntiles) {
                int4 l = lab4[(t_lo + j) * (TILE_PX / 4) + tid];
                unsigned c0 = (unsigned)l.x; if (c0 >= NCLS) c0 = 0u;  // 255 -> 0
                unsigned c1 = (unsigned)l.y; if (c1 >= NCLS) c1 = 0u;
                unsigned c2 = (unsigned)l.z; if (c2 >= NCLS) c2 = 0u;
                unsigned c3 = (unsigned)l.w; if (c3 >= NCLS) c3 = 0u;
                plab[j] = c0 | (c1 << 8) | (c2 << 16) | (c3 << 24);
            } else {
                plab[j] = 0u;
            }
        }
    }

    const float4* fbase = (const float4*)(feat + (size_t)b * DCH * HWPX);

    // slice g of group: rows at (c*GCH + g)*NTHREADS + tid
#define ZERO_GROUP() do {                                                     \
        _Pragma("unroll")                                                     \
        for (int c = 0; c < NCLS * GCH; c++)                                  \
            s_bins[c * NTHREADS + tid] = 0.0f;                                \
    } while (0)

#define PREFETCH(V, dd) do {                                                  \
        const float4* _f = fbase + (size_t)(dd) * (HWPX / 4);                 \
        _Pragma("unroll")                                                     \
        for (int j = 0; j < MAX_TILES; j++)                                   \
            if (j < ntiles) (V)[j] = __ldg(&_f[(t_lo + j) * (TILE_PX / 4) + tid]); \
    } while (0)

#define ACCUM(V, g) do {                                                      \
        _Pragma("unroll")                                                     \
        for (int j = 0; j < MAX_TILES; j++)                                   \
            if (j < ntiles) {                                                 \
                unsigned p = plab[j];                                         \
                s_bins[((p & 0xFFu) * GCH + (g)) * NTHREADS + tid]         += (V)[j].x; \
                s_bins[(((p >> 8) & 0xFFu) * GCH + (g)) * NTHREADS + tid]  += (V)[j].y; \
                s_bins[(((p >> 16) & 0xFFu) * GCH + (g)) * NTHREADS + tid] += (V)[j].z; \
                s_bins[((p >> 24) * GCH + (g)) * NTHREADS + tid]           += (V)[j].w; \
            }                                                                 \
    } while (0)

    float4 vA[MAX_TILES], vB[MAX_TILES];
    const int warp = tid >> 5, lane = tid & 31;

    // Kick off channel 0 loads; count pass runs while they're in flight.
    PREFETCH(vA, 0);

    // ---- Count pass (onehot.sum): +1.0 per pixel, uses slice 0 only.
    #pragma unroll
    for (int c = 0; c < NCLS; c++) s_bins[(c * GCH) * NTHREADS + tid] = 0.0f;
    __syncthreads();
    #pragma unroll
    for (int j = 0; j < MAX_TILES; j++) {
        if (j < ntiles) {
            unsigned p = plab[j];
            s_bins[((p & 0xFFu) * GCH) * NTHREADS + tid]         += 1.0f;
            s_bins[(((p >> 8) & 0xFFu) * GCH) * NTHREADS + tid]  += 1.0f;
            s_bins[(((p >> 16) & 0xFFu) * GCH) * NTHREADS + tid] += 1.0f;
            s_bins[((p >> 24) * GCH) * NTHREADS + tid]           += 1.0f;
        }
    }
    __syncthreads();
    for (int c = warp; c < NCLS; c += NTHREADS / 32) {
        float s = 0.0f;
        #pragma unroll
        for (int k = 0; k < NTHREADS / 32; k++)
            s += s_bins[(c * GCH) * NTHREADS + lane + k * 32];
        for (int off = 16; off; off >>= 1) s += __shfl_down_sync(0xFFFFFFFFu, s, off);
        if (lane == 0) atomicAdd(&g_counts[b][c], s);
    }
    __syncthreads();

    // ---- Channel loop: GCH=2 channels per bin group; syncs only around flush.
    for (int d = 0; d < DCH; d += GCH) {
        ZERO_GROUP();
        PREFETCH(vB, d + 1);                 // channel d already in vA
        ACCUM(vA, 0);
        if (d + GCH < DCH) PREFETCH(vA, d + GCH);   // next group in flight across flush
        ACCUM(vB, 1);
        __syncthreads();

        // Flush NCLS*GCH rows: row (c,g) -> g_sums[b][c][d+g]
        for (int cg = warp; cg < NCLS * GCH; cg += NTHREADS / 32) {
            int c = cg / GCH, g = cg % GCH;
            float s = 0.0f;
            #pragma unroll
            for (int k = 0; k < NTHREADS / 32; k++)
                s += s_bins[cg * NTHREADS + lane + k * 32];
            for (int off = 16; off; off >>= 1) s += __shfl_down_sync(0xFFFFFFFFu, s, off);
            if (lane == 0) atomicAdd(&g_sums[b][c][d + g], s);
        }
        __syncthreads();
    }
}

// ---------------------------------------------------------------------------
// Phase 2: tiny epilogue, single block. Mirrors reference math exactly.
__global__ void frc_finalize_kernel(float* __restrict__ out) {
    __shared__ float sE[NCLS - 1][DCH];
    __shared__ float s_num[NCLS];
    __shared__ float s_sq[NCLS - 1];
    __shared__ float s_cos[(NCLS - 1) * (NCLS - 1)];
    __shared__ float s_diag_m_lse[NCLS - 1];

    const int tid = threadIdx.x;
    const int K = NCLS - 1;   // 18

    if (tid < NCLS) {
        float n = 0.0f;
        for (int b = 0; b < BATCH; b++) n += (g_counts[b][tid] > 0.0f) ? 1.0f : 0.0f;
        s_num[tid] = n;
    }
    __syncthreads();

    // embedding_list[c][d] = sum_b sums[b][c][d]/(counts[b][c]+eps); E = list[1:]/num[1:]
    for (int idx = tid; idx < K * DCH; idx += NTHREADS) {
        int c = idx / DCH + 1;
        int d = idx % DCH;
        float e = 0.0f;
        for (int b = 0; b < BATCH; b++)
            e += g_sums[b][c][d] / (g_counts[b][c] + EPSF);
        sE[c - 1][d] = e / s_num[c];
    }
    __syncthreads();

    if (tid < K) {
        float s = 0.0f;
        for (int d = 0; d < DCH; d++) { float x = sE[tid][d]; s += x * x; }
        s_sq[tid] = s;
    }
    __syncthreads();

    // cos[i][j] = dot(Ei,Ej) / (sq[i]*sq[j])   (faithful: squared norms, no sqrt)
    for (int idx = tid; idx < K * K; idx += NTHREADS) {
        int i = idx / K, j = idx % K;
        float s = 0.0f;
        for (int d = 0; d < DCH; d++) s += sE[i][d] * sE[j][d];
        s_cos[idx] = s / (s_sq[i] * s_sq[j]);
    }
    __syncthreads();

    if (tid < K) {
        float m = -1e30f;
        for (int j = 0; j < K; j++) m = fmaxf(m, s_cos[tid * K + j]);
        float s = 0.0f;
        for (int j = 0; j < K; j++) s += expf(s_cos[tid * K + j] - m);
        float lse = m + logf(s);
        s_diag_m_lse[tid] = s_cos[tid * K + tid] - lse;
    }
    __syncthreads();

    if (tid == 0) {
        float t = 0.0f;
        for (int i = 0; i < K; i++) t += s_diag_m_lse[i];
        out[0] = -t / (float)K;
    }
}

// ---------------------------------------------------------------------------
extern "C" void kernel_launch(void* const* d_in, const int* in_sizes, int n_in,
                              void* d_out, int out_size) {
    const float* feat;
    const int* label;
    // Identify inputs by element count (robust to metadata ordering).
    if (in_sizes[0] == BATCH * DCH * HWPX) {
        feat  = (const float*)d_in[0];
        label = (const int*)d_in[1];
    } else {
        feat  = (const float*)d_in[1];
        label = (const int*)d_in[0];
    }

    frc_zero_kernel<<<1, NTHREADS>>>();
    frc_accum_kernel<<<NBLOCKS, NTHREADS>>>(feat, label);
    frc_finalize_kernel<<<1, NTHREADS>>>((float*)d_out);
}